// round 1
// baseline (speedup 1.0000x reference)
#include <cuda_runtime.h>
#include <cuda_bf16.h>
#include <math.h>

// Problem constants (static shapes from setup_inputs)
#define BLOCK_SIZE 2048   // B
#define EMB_DIM    256    // D
#define K_ITERS    (EMB_DIM / 2 - 1)   // 127

// Scatter kernel: one block per position p, one thread per i in [0, K).
// Writes only the nonzero entries of R[p] on top of a zeroed buffer.
//   R[p, 2i,   2i  ] =  cos(p * theta_i)
//   R[p, 2i,   2i+2] = -sin(p * theta_i)
//   R[p, 2i+2, 2i  ] =  sin(p * theta_i)
//   R[p, 2K,   2K  ] =  cos(p * theta_{K-1})   (surviving overwrite)
__global__ void rope_scatter_kernel(float* __restrict__ out) {
    const int p = blockIdx.x;            // 0 .. B-1
    const int i = threadIdx.x;           // 0 .. 127 (only i < K active)
    if (i >= K_ITERS) return;

    // theta_i = 10000 ^ (-2*(i-1)/D), computed in double then rounded to fp32
    // so the fp32 phase p*theta matches the reference to ~1 ulp.
    const double e  = -2.0 * ((double)i - 1.0) / (double)EMB_DIM;
    const float theta = (float)exp(e * 9.210340371976184);  // ln(10000)

    const float m = (float)p * theta;
    float s, c;
    __sincosf(m, &s, &c);     // fast path; refine below if needed
    // Use accurate sincos: the kernel is tiny and memset dominates, so pay
    // full-precision argument reduction for |m| up to ~2200.
    s = sinf(m);
    c = cosf(m);

    float* base = out + (size_t)p * (EMB_DIM * EMB_DIM);
    const int r = 2 * i;

    base[(size_t)r * EMB_DIM + r]           = c;    // diag
    base[(size_t)r * EMB_DIM + r + 2]       = -s;   // superdiag (+2)
    base[(size_t)(r + 2) * EMB_DIM + r]     = s;    // subdiag (-2)

    if (i == K_ITERS - 1) {
        const int rr = 2 * K_ITERS;  // 254
        base[(size_t)rr * EMB_DIM + rr] = c;        // surviving last-iter diag
    }
}

extern "C" void kernel_launch(void* const* d_in, const int* in_sizes, int n_in,
                              void* d_out, int out_size) {
    (void)d_in; (void)in_sizes; (void)n_in;

    float* out = (float*)d_out;
    const size_t bytes = (size_t)out_size * sizeof(float);

    // Phase 1: zero the entire 512 MiB output at hardware memset bandwidth.
    cudaMemsetAsync(d_out, 0, bytes, 0);

    // Phase 2: scatter the ~782K nonzero sin/cos values.
    rope_scatter_kernel<<<BLOCK_SIZE, 128, 0, 0>>>(out);
}